// round 10
// baseline (speedup 1.0000x reference)
#include <cuda_runtime.h>
#include <math.h>

// EyesMouthLoss: mean(|pred-target| * (1 + priority*299))
// priority = clip(eye + mouth, 0, 1); region = max_j clip(1 - dist_j/15, 0, 1)
//
// Algebra 1: max_j clip(1 - d_j/R) == clip(1 - sqrt(min_j d_j^2)/R) (2 sqrts/px)
// Algebra 2 (R10): weight distributes over channels:
//     acc = sum_k s_k * wgt_k,  s_k = sum_c |pred-target|_ck
//   -> load consumption needs NO weights: all 6 float4 loads front-batched
//      (MLP_p1=6), consumed immediately into s[4] (short reg lifetimes),
//      weight phase runs afterwards register-only.
// Pruning: landmark only touches rows with (y-cy)^2 < R^2; warp-autonomous
//      prescan via ballot + ffs/shfl (no barriers, no smem atomics).
// Tail: block reduce + pre-scaled fire-and-forget f32 REDG; out zeroed by an
//      async memset graph node.

#define H 512
#define W 512
#define C 3
#define B 16
#define NBLK (B * H)               // 8192 blocks, 1 row each
#define RADIUS2 225.0f
#define INV_R (1.0f / 15.0f)
#define INV_N (1.0f / (16.0f * 3.0f * 512.0f * 512.0f))
#define FULL 0xFFFFFFFFu

__global__ void __launch_bounds__(128, 14) eml_main(
    const float* __restrict__ pred,
    const float* __restrict__ target,
    const int*   __restrict__ lm,
    float* __restrict__ out)
{
    const int tid  = threadIdx.x;
    const int wid  = tid >> 5;             // 0..3 (quarter of row)
    const int lane = tid & 31;
    const int row  = blockIdx.x;           // b*H + y
    const int b    = row >> 9;
    const int y    = row & (H - 1);
    const int x0   = (wid << 7) + (lane << 2);

    // ---- front-batch ALL loads: 6x LDG.128 + 1x LDG.64 (max MLP) ----
    const size_t rowbase = (size_t)b * (C * H * W) + (size_t)y * W + x0;
    const float4 pv0 = *reinterpret_cast<const float4*>(pred   + rowbase);
    const float4 tv0 = *reinterpret_cast<const float4*>(target + rowbase);
    const float4 pv1 = *reinterpret_cast<const float4*>(pred   + rowbase + (size_t)(H * W));
    const float4 tv1 = *reinterpret_cast<const float4*>(target + rowbase + (size_t)(H * W));
    const float4 pv2 = *reinterpret_cast<const float4*>(pred   + rowbase + (size_t)(2 * H * W));
    const float4 tv2 = *reinterpret_cast<const float4*>(target + rowbase + (size_t)(2 * H * W));
    const int2  lxy = ((const int2*)lm)[b * 68 + 36 + lane];   // landmark 36+lane

    // ---- consume pairs immediately into s[4] (no weight dependency) ----
    float s0, s1, s2, s3;
    s0 = fabsf(pv0.x - tv0.x);
    s1 = fabsf(pv0.y - tv0.y);
    s2 = fabsf(pv0.z - tv0.z);
    s3 = fabsf(pv0.w - tv0.w);
    s0 += fabsf(pv1.x - tv1.x);
    s1 += fabsf(pv1.y - tv1.y);
    s2 += fabsf(pv1.z - tv1.z);
    s3 += fabsf(pv1.w - tv1.w);
    s0 += fabsf(pv2.x - tv2.x);
    s1 += fabsf(pv2.y - tv2.y);
    s2 += fabsf(pv2.z - tv2.z);
    s3 += fabsf(pv2.w - tv2.w);

    // ---- warp-level landmark prescan (register-only from here) ----
    const float cx = fminf(fmaxf((float)lxy.x, 0.0f), (float)(W - 1));
    const float cy = fminf(fmaxf((float)lxy.y, 0.0f), (float)(H - 1));
    const float dy  = (float)y - cy;
    const float dy2 = dy * dy;
    const unsigned amask = __ballot_sync(FULL, dy2 < RADIUS2);
    const unsigned emask = amask & 0x00000FFFu;        // lanes 0..11  -> lm 36..47
    const unsigned mmask = amask & 0xFFFFF000u;        // lanes 12..31 -> lm 48..67

    float acc;
    if (amask) {
        float emn[4], mmn[4];
#pragma unroll
        for (int k = 0; k < 4; k++) { emn[k] = 3.0e8f; mmn[k] = 3.0e8f; }

        unsigned m = emask;
        while (m) {
            const int j = __ffs(m) - 1; m &= m - 1;
            const float cxj = __shfl_sync(FULL, cx,  j);
            const float d2j = __shfl_sync(FULL, dy2, j);
#pragma unroll
            for (int k = 0; k < 4; k++) {
                const float dx = (float)(x0 + k) - cxj;
                emn[k] = fminf(emn[k], fmaf(dx, dx, d2j));
            }
        }
        m = mmask;
        while (m) {
            const int j = __ffs(m) - 1; m &= m - 1;
            const float cxj = __shfl_sync(FULL, cx,  j);
            const float d2j = __shfl_sync(FULL, dy2, j);
#pragma unroll
            for (int k = 0; k < 4; k++) {
                const float dx = (float)(x0 + k) - cxj;
                mmn[k] = fminf(mmn[k], fmaf(dx, dx, d2j));
            }
        }

        float wgt[4];
#pragma unroll
        for (int k = 0; k < 4; k++) {
            const float e  = (emn[k] < RADIUS2) ? (1.0f - sqrtf(emn[k]) * INV_R) : 0.0f;
            const float mm = (mmn[k] < RADIUS2) ? (1.0f - sqrtf(mmn[k]) * INV_R) : 0.0f;
            const float p  = fminf(e + mm, 1.0f);
            wgt[k] = fmaf(p, 299.0f, 1.0f);
        }
        acc = s0 * wgt[0];
        acc = fmaf(s1, wgt[1], acc);
        acc = fmaf(s2, wgt[2], acc);
        acc = fmaf(s3, wgt[3], acc);
    } else {
        acc = s0 + s1 + s2 + s3;           // all weights are 1
    }

    // ---- block reduce (single barrier) ----
#pragma unroll
    for (int s = 16; s > 0; s >>= 1)
        acc += __shfl_xor_sync(FULL, acc, s);

    __shared__ float s_part[4];
    if (lane == 0) s_part[wid] = acc;
    __syncthreads();

    if (tid == 0) {
        const float bs = s_part[0] + s_part[1] + s_part[2] + s_part[3];
        atomicAdd(out, bs * INV_N);   // fire-and-forget REDG
    }
}

extern "C" void kernel_launch(void* const* d_in, const int* in_sizes, int n_in,
                              void* d_out, int out_size)
{
    const float* pred   = (const float*)d_in[0];
    const float* target = (const float*)d_in[1];
    const int*   lmk    = (const int*)d_in[2];
    float* out = (float*)d_out;

    cudaMemsetAsync(out, 0, sizeof(float), 0);   // memset node, graph-capturable
    eml_main<<<NBLK, 128>>>(pred, target, lmk, out);
}

// round 11
// speedup vs baseline: 1.0905x; 1.0905x over previous
#include <cuda_runtime.h>
#include <math.h>

// EyesMouthLoss: mean(|pred-target| * (1 + priority*299))
// priority = clip(eye + mouth, 0, 1); region = max_j clip(1 - dist_j/15, 0, 1)
//
// Algebra 1: max_j clip(1 - d_j/R) == clip(1 - sqrt(min_j d_j^2)/R) (2 sqrts/px)
// Algebra 2: weight distributes over channels: acc = sum_k s_k*wgt_k,
//            s_k = sum_c |pred-target|_ck  -> consume needs no weights.
// R11: 8 rows per block (grid=1024, single wave). Rolled software pipeline:
//      consume(r) -> issue loads(r+1) -> weight(r). Next row's 6 LDG.128 are
//      in flight across the back-edge and through every weight phase, so the
//      DRAM pipe stays fed continuously; tail costs amortized 8x. Landmarks
//      loaded once per block (same image). Warp-autonomous prescan
//      (ballot + ffs/shfl), no prescan barriers.
// Tail: block reduce + pre-scaled fire-and-forget f32 REDG; out zeroed by an
//      async memset graph node.

#define H 512
#define W 512
#define C 3
#define B 16
#define RPB 8                      // rows per block
#define NBLK (B * H / RPB)         // 1024
#define RADIUS2 225.0f
#define INV_R (1.0f / 15.0f)
#define INV_N (1.0f / (16.0f * 3.0f * 512.0f * 512.0f))
#define FULL 0xFFFFFFFFu

__global__ void __launch_bounds__(128, 10) eml_main(
    const float* __restrict__ pred,
    const float* __restrict__ target,
    const int*   __restrict__ lm,
    float* __restrict__ out)
{
    const int tid  = threadIdx.x;
    const int wid  = tid >> 5;             // 0..3 (quarter of row)
    const int lane = tid & 31;
    const int row0 = blockIdx.x * RPB;     // first global row (b*H + y0)
    const int b    = row0 >> 9;            // 512 % RPB == 0: no image straddle
    const int y0   = row0 & (H - 1);
    const int x0   = (wid << 7) + (lane << 2);

    // ---- landmarks once per block (same image for all RPB rows) ----
    const int2 lxy = ((const int2*)lm)[b * 68 + 36 + lane];   // lm 36+lane
    const float cx = fminf(fmaxf((float)lxy.x, 0.0f), (float)(W - 1));
    const float cy = fminf(fmaxf((float)lxy.y, 0.0f), (float)(H - 1));

    const size_t base = (size_t)b * (C * H * W) + (size_t)y0 * W + x0;

    // ---- prologue: loads for row 0 ----
    float4 pv0 = *reinterpret_cast<const float4*>(pred   + base);
    float4 tv0 = *reinterpret_cast<const float4*>(target + base);
    float4 pv1 = *reinterpret_cast<const float4*>(pred   + base + (size_t)(H * W));
    float4 tv1 = *reinterpret_cast<const float4*>(target + base + (size_t)(H * W));
    float4 pv2 = *reinterpret_cast<const float4*>(pred   + base + (size_t)(2 * H * W));
    float4 tv2 = *reinterpret_cast<const float4*>(target + base + (size_t)(2 * H * W));

    float acc = 0.0f;

    for (int r = 0; r < RPB; r++) {
        // ---- consume current row's loads into s[4] (weight-independent) ----
        float s0 = fabsf(pv0.x - tv0.x);
        float s1 = fabsf(pv0.y - tv0.y);
        float s2 = fabsf(pv0.z - tv0.z);
        float s3 = fabsf(pv0.w - tv0.w);
        s0 += fabsf(pv1.x - tv1.x);
        s1 += fabsf(pv1.y - tv1.y);
        s2 += fabsf(pv1.z - tv1.z);
        s3 += fabsf(pv1.w - tv1.w);
        s0 += fabsf(pv2.x - tv2.x);
        s1 += fabsf(pv2.y - tv2.y);
        s2 += fabsf(pv2.z - tv2.z);
        s3 += fabsf(pv2.w - tv2.w);

        // ---- issue next row's loads (in flight through the weight phase) ----
        if (r < RPB - 1) {
            const size_t nb = base + (size_t)(r + 1) * W;
            pv0 = *reinterpret_cast<const float4*>(pred   + nb);
            tv0 = *reinterpret_cast<const float4*>(target + nb);
            pv1 = *reinterpret_cast<const float4*>(pred   + nb + (size_t)(H * W));
            tv1 = *reinterpret_cast<const float4*>(target + nb + (size_t)(H * W));
            pv2 = *reinterpret_cast<const float4*>(pred   + nb + (size_t)(2 * H * W));
            tv2 = *reinterpret_cast<const float4*>(target + nb + (size_t)(2 * H * W));
        }

        // ---- weight phase for row y0+r (register/shfl only) ----
        const float dy  = (float)(y0 + r) - cy;
        const float dy2 = dy * dy;
        const unsigned amask = __ballot_sync(FULL, dy2 < RADIUS2);

        if (amask) {
            const unsigned emask = amask & 0x00000FFFu;   // lanes 0..11 -> lm 36..47
            const unsigned mmask = amask & 0xFFFFF000u;   // lanes 12..31 -> lm 48..67
            float emn[4], mmn[4];
#pragma unroll
            for (int k = 0; k < 4; k++) { emn[k] = 3.0e8f; mmn[k] = 3.0e8f; }

            unsigned m = emask;
            while (m) {
                const int j = __ffs(m) - 1; m &= m - 1;
                const float cxj = __shfl_sync(FULL, cx,  j);
                const float d2j = __shfl_sync(FULL, dy2, j);
#pragma unroll
                for (int k = 0; k < 4; k++) {
                    const float dx = (float)(x0 + k) - cxj;
                    emn[k] = fminf(emn[k], fmaf(dx, dx, d2j));
                }
            }
            m = mmask;
            while (m) {
                const int j = __ffs(m) - 1; m &= m - 1;
                const float cxj = __shfl_sync(FULL, cx,  j);
                const float d2j = __shfl_sync(FULL, dy2, j);
#pragma unroll
                for (int k = 0; k < 4; k++) {
                    const float dx = (float)(x0 + k) - cxj;
                    mmn[k] = fminf(mmn[k], fmaf(dx, dx, d2j));
                }
            }

            float sw = 0.0f;
#pragma unroll
            for (int k = 0; k < 4; k++) {
                const float e  = (emn[k] < RADIUS2) ? (1.0f - sqrtf(emn[k]) * INV_R) : 0.0f;
                const float mm = (mmn[k] < RADIUS2) ? (1.0f - sqrtf(mmn[k]) * INV_R) : 0.0f;
                const float p  = fminf(e + mm, 1.0f);
                const float wk = fmaf(p, 299.0f, 1.0f);
                const float sk = (k == 0) ? s0 : (k == 1) ? s1 : (k == 2) ? s2 : s3;
                sw = fmaf(sk, wk, sw);
            }
            acc += sw;
        } else {
            acc += s0 + s1 + s2 + s3;     // all weights are 1
        }
    }

    // ---- block reduce (single barrier) ----
#pragma unroll
    for (int s = 16; s > 0; s >>= 1)
        acc += __shfl_xor_sync(FULL, acc, s);

    __shared__ float s_part[4];
    if (lane == 0) s_part[wid] = acc;
    __syncthreads();

    if (tid == 0) {
        const float bs = s_part[0] + s_part[1] + s_part[2] + s_part[3];
        atomicAdd(out, bs * INV_N);   // fire-and-forget REDG
    }
}

extern "C" void kernel_launch(void* const* d_in, const int* in_sizes, int n_in,
                              void* d_out, int out_size)
{
    const float* pred   = (const float*)d_in[0];
    const float* target = (const float*)d_in[1];
    const int*   lmk    = (const int*)d_in[2];
    float* out = (float*)d_out;

    cudaMemsetAsync(out, 0, sizeof(float), 0);   // memset node, graph-capturable
    eml_main<<<NBLK, 128>>>(pred, target, lmk, out);
}